// round 3
// baseline (speedup 1.0000x reference)
#include <cuda_runtime.h>
#include <math.h>

#define BB 32
#define TT 256
#define FF 2048
#define KK 16
#define NCC 10
#define SLICES 4        // CTAs per row
#define NTHR 128        // 4 warps

__device__ float g_part[2 * BB][SLICES];   // sum-of-squares partials (plain stores)
__device__ float g_vls[2 * BB];
__device__ unsigned int g_count = 0;

__global__ void __launch_bounds__(NTHR, 8) fused_kernel(
    const float* __restrict__ abn_fm,
    const float* __restrict__ nor_fm,
    const float* __restrict__ abn_ft,
    const float* __restrict__ nor_ft,
    const float* __restrict__ abn_sls,
    const float* __restrict__ nor_sls,
    const float* __restrict__ abn_dm,
    const float* __restrict__ nor_dm,
    const float* __restrict__ label,
    float* __restrict__ out)
{
    const int bid   = blockIdx.x;          // 0..255
    const int row   = bid >> 2;            // 0..63
    const int slice = bid & (SLICES - 1);  // 0..3
    const int b     = row & (BB - 1);
    const bool is_abn = (row < BB);

    const float* fm  = is_abn ? abn_fm  : nor_fm;
    const float* dm  = is_abn ? abn_dm  : nor_dm;
    const float* sls = is_abn ? abn_sls : nor_sls;
    const float* ft  = (is_abn ? abn_ft : nor_ft)
                     + (size_t)(NCC - 1) * BB * TT * FF + (size_t)b * TT * FF;

    const int tid  = threadIdx.x;
    const int wid  = tid >> 5;
    const int lane = tid & 31;

    // ---- load drop values: lane l, slot j -> t = j*32 + l ; key = float bits (u32,
    //      monotone for v >= 0) ----
    unsigned int key[8];
    #pragma unroll
    for (int j = 0; j < 8; j++) {
        int t = j * 32 + lane;
        float v = fm[b * TT + t] * dm[b * TT + t];
        key[j] = __float_as_uint(v);
    }

    // ---- per-warp redundant top-16 via REDUX (no barriers) ----
    int idxs[KK];
    unsigned int myidx = 0;      // lane k holds selected index of round k
    #pragma unroll
    for (int k = 0; k < KK; k++) {
        unsigned int m = key[0];
        #pragma unroll
        for (int j = 1; j < 8; j++) m = max(m, key[j]);
        m = __reduce_max_sync(0xFFFFFFFFu, m);
        unsigned int cand = 0xFFFFFFFFu;
        #pragma unroll
        for (int j = 0; j < 8; j++)
            if (key[j] == m) cand = min(cand, (unsigned int)(j * 32 + lane));
        cand = __reduce_min_sync(0xFFFFFFFFu, cand);
        idxs[k] = (int)cand;
        if (lane == k) myidx = cand;
        #pragma unroll
        for (int j = 0; j < 8; j++)
            if (key[j] == m && (unsigned int)(j * 32 + lane) == cand) key[j] = 0u;
    }

    // ---- sls mean over selected (warp 0 of slice 0 only) ----
    if (slice == 0 && wid == 0) {
        float v = (lane < KK) ? sls[b * TT + (int)myidx] : 0.0f;
        #pragma unroll
        for (int off = 16; off > 0; off >>= 1)
            v += __shfl_xor_sync(0xFFFFFFFFu, v, off);
        if (lane == 0) g_vls[row] = v * (1.0f / KK);
    }

    // ---- feature gather: this CTA owns f4 range [slice*128, slice*128+128) ----
    const float4* ft4 = (const float4*)ft;
    const int f4 = slice * 128 + tid;      // one float4 per thread
    float4 acc = make_float4(0.f, 0.f, 0.f, 0.f);
    #pragma unroll
    for (int k = 0; k < KK; k++) {
        float4 v = ft4[(size_t)idxs[k] * (FF / 4) + f4];
        acc.x += v.x; acc.y += v.y; acc.z += v.z; acc.w += v.w;
    }
    float local = acc.x * acc.x + acc.y * acc.y + acc.z * acc.z + acc.w * acc.w;

    // ---- block reduce -> partial sum of squares ----
    __shared__ float swarp[4];
    __shared__ unsigned int s_last;
    #pragma unroll
    for (int off = 16; off > 0; off >>= 1)
        local += __shfl_xor_sync(0xFFFFFFFFu, local, off);
    if (lane == 0) swarp[wid] = local;
    __syncthreads();

    if (tid == 0) {
        float tot = swarp[0] + swarp[1] + swarp[2] + swarp[3];
        g_part[row][slice] = tot;
        __threadfence();
        s_last = (atomicAdd(&g_count, 1u) == 2u * BB * SLICES - 1u) ? 1u : 0u;
    }
    __syncthreads();

    // ---- last block finalizes ----
    if (s_last) {
        __threadfence();
        __shared__ float s_rt[64];
        __shared__ float s_bce[64];
        volatile float (*vpart)[SLICES] = g_part;
        volatile float* vvls = g_vls;

        if (tid < 64) {
            float rt = 0.0f;
            if (tid < BB) {
                float sa = vpart[tid][0] + vpart[tid][1] + vpart[tid][2] + vpart[tid][3];
                float sn = vpart[BB + tid][0] + vpart[BB + tid][1]
                         + vpart[BB + tid][2] + vpart[BB + tid][3];
                float la = fabsf(100.0f - sqrtf(sa) * (1.0f / KK));
                float ln = sqrtf(sn) * (1.0f / KK);
                float l = la + ln;
                rt = l * l;
            }
            // vls = concat([vls_norm, vls_abn]); norm rows are 32..63
            float v = (tid < BB) ? vvls[BB + tid] : vvls[tid - BB];
            float lab = label[tid];
            float logp   = fmaxf(logf(v),    -100.0f);
            float log1mp = fmaxf(log1pf(-v), -100.0f);
            s_rt[tid]  = rt;
            s_bce[tid] = lab * logp + (1.0f - lab) * log1mp;
        }
        __syncthreads();
        for (int s = 32; s > 0; s >>= 1) {
            if (tid < s) { s_rt[tid] += s_rt[tid + s]; s_bce[tid] += s_bce[tid + s]; }
            __syncthreads();
        }
        if (tid == 0) {
            out[0] = 1e-4f * (s_rt[0] * (1.0f / BB));
            out[1] = -s_bce[0] * (1.0f / 64.0f);
            g_count = 0;   // reset for next graph replay
        }
    }
}

extern "C" void kernel_launch(void* const* d_in, const int* in_sizes, int n_in,
                              void* d_out, int out_size)
{
    const float* abnr_fmagn = (const float*)d_in[0];
    const float* norm_fmagn = (const float*)d_in[1];
    const float* abnr_feats = (const float*)d_in[2];
    const float* norm_feats = (const float*)d_in[3];
    const float* abnr_sls   = (const float*)d_in[4];
    const float* norm_sls   = (const float*)d_in[5];
    const float* label      = (const float*)d_in[6];
    const float* drop_abn   = (const float*)d_in[7];
    const float* drop_norm  = (const float*)d_in[8];

    fused_kernel<<<2 * BB * SLICES, NTHR>>>(abnr_fmagn, norm_fmagn,
                                            abnr_feats, norm_feats,
                                            abnr_sls, norm_sls,
                                            drop_abn, drop_norm,
                                            label, (float*)d_out);
}

// round 4
// speedup vs baseline: 1.1771x; 1.1771x over previous
#include <cuda_runtime.h>
#include <math.h>

#define BB 32
#define TT 256
#define FF 2048
#define KK 16
#define NCC 10
#define SLICES 4        // CTAs per row
#define NTHR 128        // 4 warps

__device__ float g_part[2 * BB][SLICES];   // sum-of-squares partials (plain stores)
__device__ float g_vls[2 * BB];
__device__ unsigned int g_count = 0;

__global__ void fused_kernel(
    const float* __restrict__ abn_fm,
    const float* __restrict__ nor_fm,
    const float* __restrict__ abn_ft,
    const float* __restrict__ nor_ft,
    const float* __restrict__ abn_sls,
    const float* __restrict__ nor_sls,
    const float* __restrict__ abn_dm,
    const float* __restrict__ nor_dm,
    const float* __restrict__ label,
    float* __restrict__ out)
{
    const int bid   = blockIdx.x;          // 0..255
    const int row   = bid >> 2;            // 0..63
    const int slice = bid & (SLICES - 1);  // 0..3
    const int b     = row & (BB - 1);
    const bool is_abn = (row < BB);

    const float* fm  = is_abn ? abn_fm  : nor_fm;
    const float* dm  = is_abn ? abn_dm  : nor_dm;
    const float* sls = is_abn ? abn_sls : nor_sls;
    const float* ft  = (is_abn ? abn_ft : nor_ft)
                     + (size_t)(NCC - 1) * BB * TT * FF + (size_t)b * TT * FF;

    const int tid  = threadIdx.x;
    const int wid  = tid >> 5;
    const int lane = tid & 31;

    // ---- load drop values: lane l, slot j -> t = j*32 + l ----
    // key = float bits as u32 (monotone for v >= 0)
    unsigned int key[8];
    #pragma unroll
    for (int j = 0; j < 8; j++) {
        int t = j * 32 + lane;
        float v = fm[b * TT + t] * dm[b * TT + t];
        key[j] = __float_as_uint(v);
    }

    // ---- per-warp redundant top-16; gather loads issued INSIDE the loop so
    //      memory latency overlaps the selection chain ----
    const float4* ft4 = (const float4*)ft;
    const int f4 = slice * (FF / 4 / SLICES) + tid;   // one float4 per thread per row
    float4 acc = make_float4(0.f, 0.f, 0.f, 0.f);
    unsigned int myidx = 0;      // lane k holds selected index of round k

    #pragma unroll
    for (int k = 0; k < KK; k++) {
        unsigned int m = key[0];
        #pragma unroll
        for (int j = 1; j < 8; j++) m = max(m, key[j]);
        m = __reduce_max_sync(0xFFFFFFFFu, m);
        unsigned int cand = 0xFFFFFFFFu;
        #pragma unroll
        for (int j = 0; j < 8; j++)
            if (key[j] == m) cand = min(cand, (unsigned int)(j * 32 + lane));
        cand = __reduce_min_sync(0xFFFFFFFFu, cand);
        if (lane == k) myidx = cand;
        #pragma unroll
        for (int j = 0; j < 8; j++)
            if (key[j] == m && (unsigned int)(j * 32 + lane) == cand) key[j] = 0u;

        // issue this row's load immediately (independent; drains during later rounds)
        float4 v = ft4[(size_t)cand * (FF / 4) + f4];
        acc.x += v.x; acc.y += v.y; acc.z += v.z; acc.w += v.w;
    }

    // ---- sls mean over selected (warp 0 of slice 0 only) ----
    if (slice == 0 && wid == 0) {
        float v = (lane < KK) ? sls[b * TT + (int)myidx] : 0.0f;
        #pragma unroll
        for (int off = 16; off > 0; off >>= 1)
            v += __shfl_xor_sync(0xFFFFFFFFu, v, off);
        if (lane == 0) g_vls[row] = v * (1.0f / KK);
    }

    float local = acc.x * acc.x + acc.y * acc.y + acc.z * acc.z + acc.w * acc.w;

    // ---- block reduce -> partial sum of squares ----
    __shared__ float swarp[4];
    __shared__ unsigned int s_last;
    #pragma unroll
    for (int off = 16; off > 0; off >>= 1)
        local += __shfl_xor_sync(0xFFFFFFFFu, local, off);
    if (lane == 0) swarp[wid] = local;
    __syncthreads();

    if (tid == 0) {
        float tot = swarp[0] + swarp[1] + swarp[2] + swarp[3];
        g_part[row][slice] = tot;
        __threadfence();
        s_last = (atomicAdd(&g_count, 1u) == 2u * BB * SLICES - 1u) ? 1u : 0u;
    }
    __syncthreads();

    // ---- last block finalizes ----
    if (s_last) {
        __threadfence();
        __shared__ float s_rt[64];
        __shared__ float s_bce[64];
        volatile float (*vpart)[SLICES] = g_part;
        volatile float* vvls = g_vls;

        if (tid < 64) {
            float rt = 0.0f;
            if (tid < BB) {
                float sa = vpart[tid][0] + vpart[tid][1] + vpart[tid][2] + vpart[tid][3];
                float sn = vpart[BB + tid][0] + vpart[BB + tid][1]
                         + vpart[BB + tid][2] + vpart[BB + tid][3];
                float la = fabsf(100.0f - sqrtf(sa) * (1.0f / KK));
                float ln = sqrtf(sn) * (1.0f / KK);
                float l = la + ln;
                rt = l * l;
            }
            // vls = concat([vls_norm, vls_abn]); norm rows are 32..63
            float v = (tid < BB) ? vvls[BB + tid] : vvls[tid - BB];
            float lab = label[tid];
            float logp   = fmaxf(logf(v),    -100.0f);
            float log1mp = fmaxf(log1pf(-v), -100.0f);
            s_rt[tid]  = rt;
            s_bce[tid] = lab * logp + (1.0f - lab) * log1mp;
        }
        __syncthreads();
        for (int s = 32; s > 0; s >>= 1) {
            if (tid < s) { s_rt[tid] += s_rt[tid + s]; s_bce[tid] += s_bce[tid + s]; }
            __syncthreads();
        }
        if (tid == 0) {
            out[0] = 1e-4f * (s_rt[0] * (1.0f / BB));
            out[1] = -s_bce[0] * (1.0f / 64.0f);
            g_count = 0;   // reset for next graph replay
        }
    }
}

extern "C" void kernel_launch(void* const* d_in, const int* in_sizes, int n_in,
                              void* d_out, int out_size)
{
    const float* abnr_fmagn = (const float*)d_in[0];
    const float* norm_fmagn = (const float*)d_in[1];
    const float* abnr_feats = (const float*)d_in[2];
    const float* norm_feats = (const float*)d_in[3];
    const float* abnr_sls   = (const float*)d_in[4];
    const float* norm_sls   = (const float*)d_in[5];
    const float* label      = (const float*)d_in[6];
    const float* drop_abn   = (const float*)d_in[7];
    const float* drop_norm  = (const float*)d_in[8];

    fused_kernel<<<2 * BB * SLICES, NTHR>>>(abnr_fmagn, norm_fmagn,
                                            abnr_feats, norm_feats,
                                            abnr_sls, norm_sls,
                                            drop_abn, drop_norm,
                                            label, (float*)d_out);
}

// round 5
// speedup vs baseline: 1.3761x; 1.1691x over previous
#include <cuda_runtime.h>
#include <math.h>

#define BB 32
#define TT 256
#define FF 2048
#define KK 16
#define NCC 10
#define SLICES 2        // CTAs per row
#define NTHR 256        // 8 warps

__device__ float g_part[2 * BB][SLICES];
__device__ float g_vls[2 * BB];
__device__ unsigned int g_count = 0;

__global__ void fused_kernel(
    const float* __restrict__ abn_fm,
    const float* __restrict__ nor_fm,
    const float* __restrict__ abn_ft,
    const float* __restrict__ nor_ft,
    const float* __restrict__ abn_sls,
    const float* __restrict__ nor_sls,
    const float* __restrict__ abn_dm,
    const float* __restrict__ nor_dm,
    const float* __restrict__ label,
    float* __restrict__ out)
{
    const int bid   = blockIdx.x;          // 0..127
    const int row   = bid >> 1;            // 0..63
    const int slice = bid & (SLICES - 1);  // 0..1
    const int b     = row & (BB - 1);
    const bool is_abn = (row < BB);

    const float* fm  = is_abn ? abn_fm  : nor_fm;
    const float* dm  = is_abn ? abn_dm  : nor_dm;
    const float* sls = is_abn ? abn_sls : nor_sls;
    const float* ft  = (is_abn ? abn_ft : nor_ft)
                     + (size_t)(NCC - 1) * BB * TT * FF + (size_t)b * TT * FF;

    const int tid  = threadIdx.x;
    const int wid  = tid >> 5;
    const int lane = tid & 31;
    const bool vls_warp = (slice == 0 && wid == 0);

    // ---- prefetch sls row into registers (vls warp only; overlaps top-K) ----
    float sv[8];
    if (vls_warp) {
        #pragma unroll
        for (int j = 0; j < 8; j++) sv[j] = sls[b * TT + j * 32 + lane];
    }

    // ---- drop values: lane l, slot j -> t = j*32 + l ; key = float bits ----
    unsigned int key[8];
    #pragma unroll
    for (int j = 0; j < 8; j++) {
        int t = j * 32 + lane;
        float v = fm[b * TT + t] * dm[b * TT + t];
        key[j] = __float_as_uint(v);
    }

    // ---- per-warp redundant top-16 via REDUX (no barriers) ----
    int idxs[KK];
    unsigned int myidx = 0;      // lane k holds selected index of round k
    #pragma unroll
    for (int k = 0; k < KK; k++) {
        unsigned int m = key[0];
        #pragma unroll
        for (int j = 1; j < 8; j++) m = max(m, key[j]);
        m = __reduce_max_sync(0xFFFFFFFFu, m);
        unsigned int cand = 0xFFFFFFFFu;
        #pragma unroll
        for (int j = 0; j < 8; j++)
            if (key[j] == m) cand = min(cand, (unsigned int)(j * 32 + lane));
        cand = __reduce_min_sync(0xFFFFFFFFu, cand);
        idxs[k] = (int)cand;
        if (lane == k) myidx = cand;
        #pragma unroll
        for (int j = 0; j < 8; j++)
            if (key[j] == m && (unsigned int)(j * 32 + lane) == cand) key[j] = 0u;
    }

    // ---- batched gather: all 16 addresses ready -> full MLP ----
    const float4* ft4 = (const float4*)ft;
    const int f4 = slice * (FF / 4 / SLICES) + tid;   // one float4 per thread per row
    float4 acc = make_float4(0.f, 0.f, 0.f, 0.f);
    #pragma unroll
    for (int k = 0; k < KK; k++) {
        float4 v = ft4[(size_t)idxs[k] * (FF / 4) + f4];
        acc.x += v.x; acc.y += v.y; acc.z += v.z; acc.w += v.w;
    }
    float local = acc.x * acc.x + acc.y * acc.y + acc.z * acc.z + acc.w * acc.w;

    // ---- sls mean over selected: value shuffled from prefetched regs ----
    if (vls_warp) {
        int src  = (int)(myidx & 31u);
        int slot = (int)(myidx >> 5);
        float val = 0.0f;
        #pragma unroll
        for (int j = 0; j < 8; j++) {
            float t = __shfl_sync(0xFFFFFFFFu, sv[j], src);
            if (j == slot) val = t;
        }
        if (lane >= KK) val = 0.0f;
        #pragma unroll
        for (int off = 16; off > 0; off >>= 1)
            val += __shfl_xor_sync(0xFFFFFFFFu, val, off);
        if (lane == 0) g_vls[row] = val * (1.0f / KK);
    }

    // ---- block reduce -> partial sum of squares ----
    __shared__ float swarp[8];
    __shared__ unsigned int s_last;
    #pragma unroll
    for (int off = 16; off > 0; off >>= 1)
        local += __shfl_xor_sync(0xFFFFFFFFu, local, off);
    if (lane == 0) swarp[wid] = local;
    __syncthreads();

    if (tid == 0) {
        float tot = 0.0f;
        #pragma unroll
        for (int w = 0; w < 8; w++) tot += swarp[w];
        g_part[row][slice] = tot;
        __threadfence();
        s_last = (atomicAdd(&g_count, 1u) == 2u * BB * SLICES - 1u) ? 1u : 0u;
    }
    __syncthreads();

    // ---- last block finalizes ----
    if (s_last) {
        __threadfence();
        __shared__ float s_rt[64];
        __shared__ float s_bce[64];

        if (tid < 64) {
            float rt = 0.0f;
            if (tid < BB) {
                float sa = g_part[tid][0] + g_part[tid][1];
                float sn = g_part[BB + tid][0] + g_part[BB + tid][1];
                float la = fabsf(100.0f - sqrtf(sa) * (1.0f / KK));
                float ln = sqrtf(sn) * (1.0f / KK);
                float l = la + ln;
                rt = l * l;
            }
            // vls = concat([vls_norm, vls_abn]); norm rows are 32..63
            float v = (tid < BB) ? g_vls[BB + tid] : g_vls[tid - BB];
            float lab = label[tid];
            float logp   = fmaxf(logf(v),    -100.0f);
            float log1mp = fmaxf(log1pf(-v), -100.0f);
            s_rt[tid]  = rt;
            s_bce[tid] = lab * logp + (1.0f - lab) * log1mp;
        }
        __syncthreads();
        for (int s = 32; s > 0; s >>= 1) {
            if (tid < s) { s_rt[tid] += s_rt[tid + s]; s_bce[tid] += s_bce[tid + s]; }
            __syncthreads();
        }
        if (tid == 0) {
            out[0] = 1e-4f * (s_rt[0] * (1.0f / BB));
            out[1] = -s_bce[0] * (1.0f / 64.0f);
            g_count = 0;   // reset for next graph replay
        }
    }
}

extern "C" void kernel_launch(void* const* d_in, const int* in_sizes, int n_in,
                              void* d_out, int out_size)
{
    const float* abnr_fmagn = (const float*)d_in[0];
    const float* norm_fmagn = (const float*)d_in[1];
    const float* abnr_feats = (const float*)d_in[2];
    const float* norm_feats = (const float*)d_in[3];
    const float* abnr_sls   = (const float*)d_in[4];
    const float* norm_sls   = (const float*)d_in[5];
    const float* label      = (const float*)d_in[6];
    const float* drop_abn   = (const float*)d_in[7];
    const float* drop_norm  = (const float*)d_in[8];

    fused_kernel<<<2 * BB * SLICES, NTHR>>>(abnr_fmagn, norm_fmagn,
                                            abnr_feats, norm_feats,
                                            abnr_sls, norm_sls,
                                            drop_abn, drop_norm,
                                            label, (float*)d_out);
}